// round 1
// baseline (speedup 1.0000x reference)
#include <cuda_runtime.h>
#include <cstdint>

// out[b, 0:128]   = x[b, :]           for b < B
// out[b, 128:256] = sum_{e: dst[e]==b} x[src[e], :]
//
// Kernel 1: copy first half + zero second half (float4 per thread).
// Kernel 2: one warp per edge, vectorized gather + red.global.add.v4.f32.

#define NFEAT 128          // floats per x row
#define ROW_OUT 256        // floats per out row

__global__ void init_out_kernel(const float* __restrict__ x,
                                float* __restrict__ out,
                                int B) {
    int idx = blockIdx.x * blockDim.x + threadIdx.x;   // over B * 64 float4s
    int total = B * (ROW_OUT / 4);
    if (idx >= total) return;
    int row = idx >> 6;          // /64
    int c4  = idx & 63;          // float4 index within the 256-float row
    float4 v;
    if (c4 < (NFEAT / 4)) {
        v = reinterpret_cast<const float4*>(x)[(size_t)row * (NFEAT / 4) + c4];
    } else {
        v = make_float4(0.f, 0.f, 0.f, 0.f);
    }
    reinterpret_cast<float4*>(out)[(size_t)row * (ROW_OUT / 4) + c4] = v;
}

__global__ void scatter_edges_kernel(const float* __restrict__ x,
                                     const int* __restrict__ edge_index,
                                     float* __restrict__ out,
                                     int E, int B) {
    int gtid = blockIdx.x * blockDim.x + threadIdx.x;
    int warp = gtid >> 5;
    int lane = gtid & 31;
    if (warp >= E) return;

    int dst = __ldg(edge_index + E + warp);   // edge_index[1][warp]
    if ((unsigned)dst >= (unsigned)B) return;
    int src = __ldg(edge_index + warp);       // edge_index[0][warp]

    float4 v = reinterpret_cast<const float4*>(x + (size_t)src * NFEAT)[lane];
    float* p = out + (size_t)dst * ROW_OUT + NFEAT + lane * 4;
    asm volatile("red.global.add.v4.f32 [%0], {%1, %2, %3, %4};"
                 :: "l"(p), "f"(v.x), "f"(v.y), "f"(v.z), "f"(v.w)
                 : "memory");
}

extern "C" void kernel_launch(void* const* d_in, const int* in_sizes, int n_in,
                              void* d_out, int out_size) {
    const float* x         = (const float*)d_in[0];
    const int*   edge_idx  = (const int*)d_in[1];
    // d_in[2] is the batch_size scalar on device; B is derivable on host:
    float*       out       = (float*)d_out;

    int B = out_size / ROW_OUT;          // 50000
    int E = in_sizes[1] / 2;             // 640000

    // Kernel 1: init output (copy + zero)
    {
        int total = B * (ROW_OUT / 4);
        int threads = 256;
        int blocks = (total + threads - 1) / threads;
        init_out_kernel<<<blocks, threads>>>(x, out, B);
    }

    // Kernel 2: scatter-add, one warp per edge
    {
        int threads = 256;                       // 8 warps/block
        long long total_threads = (long long)E * 32;
        int blocks = (int)((total_threads + threads - 1) / threads);
        scatter_edges_kernel<<<blocks, threads>>>(x, edge_idx, out, E, B);
    }
}

// round 2
// speedup vs baseline: 1.5762x; 1.5762x over previous
#include <cuda_runtime.h>
#include <cstdint>

// out[b, 0:128]   = x[b, :]                       for b < B
// out[b, 128:256] = sum_{e: dst[e]==b} x[src[e]]
//
// Pipeline:
//   K1 init_out:   copy first half + zero second half; zero edge counter.
//   K2 compact:    filter edges with dst < B into g_edges via warp-aggregated atomics.
//   K3 scatter:    32 all-valid edges per warp, fully unrolled shfl->gather->red.v4.

#define NFEAT 128
#define ROW_OUT 256
#define MAX_E 640000
#define EPW 32          // edges per warp in scatter

__device__ int2 g_edges[MAX_E];
__device__ int  g_count;

__global__ void init_out_kernel(const float* __restrict__ x,
                                float* __restrict__ out,
                                int B) {
    int idx = blockIdx.x * blockDim.x + threadIdx.x;   // over B * 64 float4s
    if (idx == 0) g_count = 0;
    int total = B * (ROW_OUT / 4);
    if (idx >= total) return;
    int row = idx >> 6;
    int c4  = idx & 63;
    float4 v;
    if (c4 < (NFEAT / 4)) {
        v = reinterpret_cast<const float4*>(x)[(size_t)row * (NFEAT / 4) + c4];
    } else {
        v = make_float4(0.f, 0.f, 0.f, 0.f);
    }
    reinterpret_cast<float4*>(out)[(size_t)row * (ROW_OUT / 4) + c4] = v;
}

__global__ void compact_kernel(const int* __restrict__ ei, int E, int B) {
    int i = blockIdx.x * blockDim.x + threadIdx.x;
    if (i >= E) return;
    int d = __ldg(ei + E + i);
    if ((unsigned)d < (unsigned)B) {
        int s = __ldg(ei + i);
        int pos = atomicAdd(&g_count, 1);   // nvcc warp-aggregates this
        g_edges[pos] = make_int2(s, d);
    }
}

__global__ void scatter_compact_kernel(const float* __restrict__ x,
                                       float* __restrict__ out) {
    int nvalid = g_count;
    int warp = (blockIdx.x * blockDim.x + threadIdx.x) >> 5;
    int lane = threadIdx.x & 31;
    int base = warp * EPW;
    if (base >= nvalid) return;

    int2 e = make_int2(0, 0);
    if (base + lane < nvalid)
        e = __ldg(&g_edges[base + lane]);

    int rem = nvalid - base;
    if (rem >= EPW) {
        // Fast path: 32 valid edges, branch-free, fully unrolled.
        #pragma unroll
        for (int k = 0; k < EPW; k++) {
            int se = __shfl_sync(0xFFFFFFFFu, e.x, k);
            int de = __shfl_sync(0xFFFFFFFFu, e.y, k);
            float4 v = reinterpret_cast<const float4*>(
                           x + (size_t)se * NFEAT)[lane];
            float* p = out + (size_t)de * ROW_OUT + NFEAT + lane * 4;
            asm volatile("red.global.add.v4.f32 [%0], {%1, %2, %3, %4};"
                         :: "l"(p), "f"(v.x), "f"(v.y), "f"(v.z), "f"(v.w)
                         : "memory");
        }
    } else {
        // Tail: fewer than 32 edges remain.
        for (int k = 0; k < rem; k++) {
            int se = __shfl_sync(0xFFFFFFFFu, e.x, k);
            int de = __shfl_sync(0xFFFFFFFFu, e.y, k);
            float4 v = reinterpret_cast<const float4*>(
                           x + (size_t)se * NFEAT)[lane];
            float* p = out + (size_t)de * ROW_OUT + NFEAT + lane * 4;
            asm volatile("red.global.add.v4.f32 [%0], {%1, %2, %3, %4};"
                         :: "l"(p), "f"(v.x), "f"(v.y), "f"(v.z), "f"(v.w)
                         : "memory");
        }
    }
}

extern "C" void kernel_launch(void* const* d_in, const int* in_sizes, int n_in,
                              void* d_out, int out_size) {
    const float* x        = (const float*)d_in[0];
    const int*   edge_idx = (const int*)d_in[1];
    float*       out      = (float*)d_out;

    int B = out_size / ROW_OUT;          // 50000
    int E = in_sizes[1] / 2;             // 640000

    {   // K1: init output + counter
        int total = B * (ROW_OUT / 4);
        int threads = 256;
        int blocks = (total + threads - 1) / threads;
        init_out_kernel<<<blocks, threads>>>(x, out, B);
    }
    {   // K2: compact valid edges
        int threads = 256;
        int blocks = (E + threads - 1) / threads;
        compact_kernel<<<blocks, threads>>>(edge_idx, E, B);
    }
    {   // K3: scatter-add over compacted edges (sized for worst case count=E)
        int threads = 256;                              // 8 warps/block
        int warps_needed = (E + EPW - 1) / EPW;
        int blocks = (warps_needed * 32 + threads - 1) / threads;
        scatter_compact_kernel<<<blocks, threads>>>(x, out);
    }
}

// round 3
// speedup vs baseline: 2.6346x; 1.6715x over previous
#include <cuda_runtime.h>
#include <cstdint>

// out[b, 0:128]   = x[b, :]                       for b < B
// out[b, 128:256] = sum_{e: dst[e]==b} x[src[e]]
//
// Pipeline (atomic-free main path):
//   K1 zero_cnt:  zero per-row counters + overflow counter.
//   K2 bin:       ELL binning by destination (slot via atomic cursor).
//   K3 main:      one warp per row: register-accumulate gathered neighbors,
//                 fused copy of x[b] into first half. Plain STG.128 stores.
//   K4 overflow:  rare edges with degree > SLOTS via red.global.add.v4.

#define NFEAT   128
#define ROW_OUT 256
#define MAX_E   640000
#define B_MAX   65536
#define SLOTS   32

__device__ int  g_cnt[B_MAX];
__device__ int  g_ell[B_MAX * SLOTS];
__device__ int2 g_ovf[MAX_E];
__device__ int  g_ovf_count;

__global__ void zero_cnt_kernel(int B) {
    int i = blockIdx.x * blockDim.x + threadIdx.x;
    if (i == 0) g_ovf_count = 0;
    if (i < B) g_cnt[i] = 0;
}

__global__ void bin_kernel(const int* __restrict__ ei, int E, int B) {
    int i = blockIdx.x * blockDim.x + threadIdx.x;
    if (i >= E) return;
    int d = __ldg(ei + E + i);
    if ((unsigned)d < (unsigned)B) {
        int s = __ldg(ei + i);
        int k = atomicAdd(&g_cnt[d], 1);
        if (k < SLOTS) {
            g_ell[d * SLOTS + k] = s;
        } else {
            int p = atomicAdd(&g_ovf_count, 1);
            g_ovf[p] = make_int2(s, d);
        }
    }
}

__global__ void main_kernel(const float* __restrict__ x,
                            float* __restrict__ out,
                            int B) {
    int warp = (blockIdx.x * blockDim.x + threadIdx.x) >> 5;
    int lane = threadIdx.x & 31;
    if (warp >= B) return;
    int b = warp;

    int c = g_cnt[b];
    c = c < SLOTS ? c : SLOTS;

    // Coalesced preload of this row's source list (one slot per lane).
    int src_l = (lane < c) ? g_ell[b * SLOTS + lane] : 0;

    float4 acc = make_float4(0.f, 0.f, 0.f, 0.f);
    for (int k = 0; k < c; k++) {
        int se = __shfl_sync(0xFFFFFFFFu, src_l, k);
        float4 v = __ldg(reinterpret_cast<const float4*>(
                             x + (size_t)se * NFEAT) + lane);
        acc.x += v.x; acc.y += v.y; acc.z += v.z; acc.w += v.w;
    }

    // Fused: first half = x[b], second half = neighbor sum.
    float4 mine = __ldg(reinterpret_cast<const float4*>(
                            x + (size_t)b * NFEAT) + lane);
    float4* orow = reinterpret_cast<float4*>(out + (size_t)b * ROW_OUT);
    orow[lane]                = mine;
    orow[(NFEAT / 4) + lane]  = acc;
}

__global__ void overflow_kernel(const float* __restrict__ x,
                                float* __restrict__ out) {
    int n = g_ovf_count;
    int warp = (blockIdx.x * blockDim.x + threadIdx.x) >> 5;
    int lane = threadIdx.x & 31;
    // Grid-stride over overflow edges, one warp per edge.
    int nwarps = (gridDim.x * blockDim.x) >> 5;
    for (int e = warp; e < n; e += nwarps) {
        int2 ed = g_ovf[e];
        float4 v = __ldg(reinterpret_cast<const float4*>(
                             x + (size_t)ed.x * NFEAT) + lane);
        float* p = out + (size_t)ed.y * ROW_OUT + NFEAT + lane * 4;
        asm volatile("red.global.add.v4.f32 [%0], {%1, %2, %3, %4};"
                     :: "l"(p), "f"(v.x), "f"(v.y), "f"(v.z), "f"(v.w)
                     : "memory");
    }
}

extern "C" void kernel_launch(void* const* d_in, const int* in_sizes, int n_in,
                              void* d_out, int out_size) {
    const float* x        = (const float*)d_in[0];
    const int*   edge_idx = (const int*)d_in[1];
    float*       out      = (float*)d_out;

    int B = out_size / ROW_OUT;          // 50000
    int E = in_sizes[1] / 2;             // 640000

    {   // K1: zero counters
        int threads = 256;
        int blocks = (B + threads - 1) / threads;
        zero_cnt_kernel<<<blocks, threads>>>(B);
    }
    {   // K2: ELL binning
        int threads = 256;
        int blocks = (E + threads - 1) / threads;
        bin_kernel<<<blocks, threads>>>(edge_idx, E, B);
    }
    {   // K3: main fused gather-accumulate-store, one warp per row
        int threads = 256;                          // 8 warps/block
        int blocks = (B + 7) / 8;
        main_kernel<<<blocks, threads>>>(x, out, B);
    }
    {   // K4: overflow edges (expected empty; small fixed grid)
        overflow_kernel<<<32, 256>>>(x, out);
    }
}